// round 16
// baseline (speedup 1.0000x reference)
#include <cuda_runtime.h>
#include <cstdint>

// YoloLoss: y (16384,7,7,30) f32, gt same -> scalar f32.
// HBM-bound streaming reduction: 192.7 MB read, 4 B written.
// Direct thread-per-cell LDG (R8 architecture, best measured per-byte rate),
// split-phase register structure for occupancy, fused last-block finalize.

#define LAMBDA_COORD 5.0f
#define LAMBDA_NOOBJ 0.5f

static constexpr int B_SZ  = 16384;
static constexpr int NCELL = 16384 * 7 * 7;   // 802816
static constexpr int TPB   = 256;
static constexpr int NBLK  = NCELL / TPB;     // 3136 exactly, no tail

__device__ double       g_partials[NBLK];
__device__ unsigned int g_count = 0;          // self-resetting ticket

__device__ __forceinline__ float iou_f(float x1, float y1, float w1, float h1,
                                       float x2, float y2, float w2, float h2) {
    float xl = fmaxf(x1 - 0.5f * w1, x2 - 0.5f * w2);
    float yt = fmaxf(y1 - 0.5f * h1, y2 - 0.5f * h2);
    float xr = fminf(x1 + 0.5f * w1, x2 + 0.5f * w2);
    float yb = fminf(y1 + 0.5f * h1, y2 + 0.5f * h2);
    bool valid = (xr >= xl) && (yb >= yt);
    float inter = (xr - xl) * (yb - yt);
    float uni = w1 * h1 + w2 * h2 - inter;
    float safe = (uni == 0.0f) ? 1.0f : uni;
    return valid ? (inter / safe) : 0.0f;
}

// Block-wide deterministic double reduction (TPB = 256 -> 8 warps).
__device__ __forceinline__ double block_reduce(double v, double* warp_sums,
                                               int lane, int wid) {
#pragma unroll
    for (int off = 16; off > 0; off >>= 1)
        v += __shfl_down_sync(0xFFFFFFFFu, v, off);
    if (lane == 0) warp_sums[wid] = v;
    __syncthreads();
    double s = 0.0;
    if (wid == 0) {
        s = (lane < TPB / 32) ? warp_sums[lane] : 0.0;
#pragma unroll
        for (int off = 4; off > 0; off >>= 1)
            s += __shfl_down_sync(0xFFFFFFFFu, s, off);
    }
    return s;   // valid in (wid==0, lane==0)
}

__global__ __launch_bounds__(TPB) void yolo_fused_kernel(
    const float* __restrict__ y, const float* __restrict__ gt,
    float* __restrict__ out)
{
    __shared__ double warp_sums[TPB / 32];
    __shared__ int    is_last;

    const int tid  = threadIdx.x;
    const int lane = tid & 31;
    const int wid  = tid >> 5;

    const int c = blockIdx.x * TPB + tid;   // one cell per thread

    // 30 floats per cell = 120 B, 8-byte aligned -> float2 loads.
    const float2* __restrict__ yp = reinterpret_cast<const float2*>(y)  + (size_t)c * 15;
    const float2* __restrict__ tp = reinterpret_cast<const float2*>(gt) + (size_t)c * 15;

    // ---- phase 1: box/conf fields 0..9 only (keeps live regs low) ----
    float2 p01 = yp[0], p23 = yp[1], p45 = yp[2], p67 = yp[3], p89 = yp[4];
    float2 t01 = tp[0], t23 = tp[1], t45 = tp[2];

    const float t0 = t01.x, t1 = t01.y, t2 = t23.x, t3 = t23.y, t4 = t45.x;
    const float p0 = p01.x, p1 = p01.y, p2 = p23.x, p3 = p23.y, p4 = p45.x;
    const float p5 = p45.y, p6 = p67.x, p7 = p67.y, p8 = p89.x, p9 = p89.y;

    const float obj   = (t4 > 0.0f)  ? 1.0f : 0.0f;
    const float noobj = (t4 == 0.0f) ? 1.0f : 0.0f;   // NOT 1-obj (matches ref)

    float dconf = t4 - p4;
    float conf_noobj = noobj * dconf * dconf;

    float iou1 = iou_f(t0, t1, t2, t3, p0, p1, p2, p3);
    float iou2 = iou_f(t0, t1, t2, t3, p5, p6, p7, p8);
    float resp1 = (iou1 > iou2) ? 1.0f : 0.0f;
    float m1 = obj * resp1;
    float m2 = obj * (1.0f - resp1);

    float e1v = iou1 - p4;
    float e2v = iou2 - p9;
    float conf_obj = m1 * e1v * e1v + m2 * e2v * e2v;

    float dx1 = t0 - p0, dy1 = t1 - p1;
    float dx2 = t0 - p5, dy2 = t1 - p6;
    float xy = m1 * (dx1 * dx1 + dy1 * dy1) + m2 * (dx2 * dx2 + dy2 * dy2);

    float dw1 = t2 - p2, dh1 = t3 - p3;
    float dw2 = t2 - p7, dh2 = t3 - p8;
    float wh = m1 * (dw1 * dw1 + dh1 * dh1) + m2 * (dw2 * dw2 + dh2 * dh2);

    // ---- phase 2: class fields 10..29 streamed as 10 float2 per array ----
    float cls = 0.0f;
#pragma unroll
    for (int i = 5; i < 15; i++) {
        float2 a = yp[i];
        float2 b = tp[i];
        float d0 = b.x - a.x;
        float d1 = b.y - a.y;
        cls = fmaf(d0, d0, cls);
        cls = fmaf(d1, d1, cls);
    }
    cls *= obj;

    float cell = LAMBDA_COORD * (xy + wh) + conf_obj
               + LAMBDA_NOOBJ * conf_noobj + cls;

    // ---- per-block partial ----
    double bsum = block_reduce((double)cell, warp_sums, lane, wid);
    if (tid == 0) {
        g_partials[blockIdx.x] = bsum;
        __threadfence();
        unsigned old = atomicAdd(&g_count, 1u);
        is_last = (old == (unsigned)(NBLK - 1)) ? 1 : 0;
    }
    __syncthreads();

    // ---- last block: deterministic finalize, then reset ticket ----
    if (is_last) {
        double s = 0.0;
        for (int i = tid; i < NBLK; i += TPB)
            s += g_partials[i];
        double total = block_reduce(s, warp_sums, lane, wid);
        if (tid == 0) {
            out[0] = (float)(total / (double)B_SZ);
            g_count = 0;    // ready for next graph replay
        }
    }
}

extern "C" void kernel_launch(void* const* d_in, const int* in_sizes, int n_in,
                              void* d_out, int out_size)
{
    const float* y  = (const float*)d_in[0];
    const float* gt = (const float*)d_in[1];
    float* out = (float*)d_out;

    yolo_fused_kernel<<<NBLK, TPB>>>(y, gt, out);
}

// round 17
// speedup vs baseline: 1.1777x; 1.1777x over previous
#include <cuda_runtime.h>
#include <cstdint>

// YoloLoss: y (16384,7,7,30) f32, gt same -> scalar f32.
// HBM-bound streaming reduction: 192.7 MB read, 4 B written.
// R8 architecture (measured-best 5.3 TB/s): thread-per-cell, ALL 30 float2
// loads front-batched (max MLP) -> compute -> block reduce.
// Plus the validated in-kernel last-block finalize (kills 6.9us second launch).

#define LAMBDA_COORD 5.0f
#define LAMBDA_NOOBJ 0.5f

static constexpr int B_SZ  = 16384;
static constexpr int NCELL = 16384 * 7 * 7;   // 802816
static constexpr int TPB   = 256;
static constexpr int NBLK  = NCELL / TPB;     // 3136 exactly, no tail

__device__ double       g_partials[NBLK];
__device__ unsigned int g_count = 0;          // self-resetting ticket

__device__ __forceinline__ float iou_f(float x1, float y1, float w1, float h1,
                                       float x2, float y2, float w2, float h2) {
    float xl = fmaxf(x1 - 0.5f * w1, x2 - 0.5f * w2);
    float yt = fmaxf(y1 - 0.5f * h1, y2 - 0.5f * h2);
    float xr = fminf(x1 + 0.5f * w1, x2 + 0.5f * w2);
    float yb = fminf(y1 + 0.5f * h1, y2 + 0.5f * h2);
    bool valid = (xr >= xl) && (yb >= yt);
    float inter = (xr - xl) * (yb - yt);
    float uni = w1 * h1 + w2 * h2 - inter;
    float safe = (uni == 0.0f) ? 1.0f : uni;
    return valid ? (inter / safe) : 0.0f;
}

// Block-wide deterministic double reduction (TPB = 256 -> 8 warps).
__device__ __forceinline__ double block_reduce(double v, double* warp_sums,
                                               int lane, int wid) {
#pragma unroll
    for (int off = 16; off > 0; off >>= 1)
        v += __shfl_down_sync(0xFFFFFFFFu, v, off);
    if (lane == 0) warp_sums[wid] = v;
    __syncthreads();
    double s = 0.0;
    if (wid == 0) {
        s = (lane < TPB / 32) ? warp_sums[lane] : 0.0;
#pragma unroll
        for (int off = 4; off > 0; off >>= 1)
            s += __shfl_down_sync(0xFFFFFFFFu, s, off);
    }
    return s;   // valid in (wid==0, lane==0)
}

__global__ __launch_bounds__(TPB) void yolo_fused_kernel(
    const float* __restrict__ y, const float* __restrict__ gt,
    float* __restrict__ out)
{
    __shared__ double warp_sums[TPB / 32];
    __shared__ int    is_last;

    const int tid  = threadIdx.x;
    const int lane = tid & 31;
    const int wid  = tid >> 5;

    const int c = blockIdx.x * TPB + tid;   // one cell per thread

    // 30 floats per cell = 120 B, 8-byte aligned for every cell -> float2 loads.
    // ALL loads issued up front (two unrolled loops) so ptxas front-batches
    // them: MLP ~30, long-scoreboard latency fully overlapped. (R16 proved
    // interleaving loads with the FMA chain drops MLP to ~2 and costs 45%.)
    const float2* __restrict__ yp = reinterpret_cast<const float2*>(y)  + (size_t)c * 15;
    const float2* __restrict__ tp = reinterpret_cast<const float2*>(gt) + (size_t)c * 15;

    float p[30], t[30];
#pragma unroll
    for (int i = 0; i < 15; i++) { float2 v = yp[i]; p[2*i] = v.x; p[2*i+1] = v.y; }
#pragma unroll
    for (int i = 0; i < 15; i++) { float2 v = tp[i]; t[2*i] = v.x; t[2*i+1] = v.y; }

    const float obj   = (t[4] > 0.0f)  ? 1.0f : 0.0f;
    const float noobj = (t[4] == 0.0f) ? 1.0f : 0.0f;   // NOT 1-obj (matches ref)

    float class_loss = 0.0f;
#pragma unroll
    for (int d = 10; d < 30; d++) {
        float df = t[d] - p[d];
        class_loss = fmaf(df, df, class_loss);
    }
    class_loss *= obj;

    float dconf = t[4] - p[4];
    float conf_noobj = noobj * dconf * dconf;

    float iou1 = iou_f(t[0], t[1], t[2], t[3], p[0], p[1], p[2], p[3]);
    float iou2 = iou_f(t[0], t[1], t[2], t[3], p[5], p[6], p[7], p[8]);
    float resp1 = (iou1 > iou2) ? 1.0f : 0.0f;
    float m1 = obj * resp1;
    float m2 = obj * (1.0f - resp1);

    float e1v = iou1 - p[4];
    float e2v = iou2 - p[9];
    float conf_obj = m1 * e1v * e1v + m2 * e2v * e2v;

    float dx1 = t[0] - p[0], dy1 = t[1] - p[1];
    float dx2 = t[0] - p[5], dy2 = t[1] - p[6];
    float xy = m1 * (dx1 * dx1 + dy1 * dy1) + m2 * (dx2 * dx2 + dy2 * dy2);

    float dw1 = t[2] - p[2], dh1 = t[3] - p[3];
    float dw2 = t[2] - p[7], dh2 = t[3] - p[8];
    float wh = m1 * (dw1 * dw1 + dh1 * dh1) + m2 * (dw2 * dw2 + dh2 * dh2);

    float cell = LAMBDA_COORD * (xy + wh) + conf_obj
               + LAMBDA_NOOBJ * conf_noobj + class_loss;

    // ---- per-block partial ----
    double bsum = block_reduce((double)cell, warp_sums, lane, wid);
    if (tid == 0) {
        g_partials[blockIdx.x] = bsum;
        __threadfence();
        unsigned old = atomicAdd(&g_count, 1u);
        is_last = (old == (unsigned)(NBLK - 1)) ? 1 : 0;
    }
    __syncthreads();

    // ---- last block: deterministic finalize, then reset ticket ----
    if (is_last) {
        double s = 0.0;
        for (int i = tid; i < NBLK; i += TPB)
            s += g_partials[i];
        double total = block_reduce(s, warp_sums, lane, wid);
        if (tid == 0) {
            out[0] = (float)(total / (double)B_SZ);
            g_count = 0;    // ready for next graph replay
        }
    }
}

extern "C" void kernel_launch(void* const* d_in, const int* in_sizes, int n_in,
                              void* d_out, int out_size)
{
    const float* y  = (const float*)d_in[0];
    const float* gt = (const float*)d_in[1];
    float* out = (float*)d_out;

    yolo_fused_kernel<<<NBLK, TPB>>>(y, gt, out);
}